// round 2
// baseline (speedup 1.0000x reference)
#include <cuda_runtime.h>

#define Tlen  8192
#define Bsz   4
#define RES   256
#define SKIPC 512
#define NCLSC 256
#define NLAY  30
#define WIN   3072
#define HSTR  3200
#define KT    32
#define ASTR2 544
#define MR    16
#define NPT   6

typedef unsigned long long ull;

// ---------------- device scratch (allocation-free) ----------------
__device__ float g_h[2][Bsz][RES][HSTR];     // ping-pong hidden state; pads stay zero
__device__ float g_gLast[NLAY][Bsz][RES];    // gated activation at t = T-1 per layer
__device__ float g_skip[Bsz][SKIPC];         // relu(skip_sum) at t = T-1

// ---------------- f32x2 helpers ----------------
__device__ __forceinline__ ull pk2(float v) {
    ull r; asm("mov.b64 %0, {%1,%2};" : "=l"(r) : "f"(v), "f"(v)); return r;
}
__device__ __forceinline__ ull fma2(ull a, ull b, ull c) {
    ull d; asm("fma.rn.f32x2 %0, %1, %2, %3;" : "=l"(d) : "l"(a), "l"(b), "l"(c)); return d;
}
__device__ __forceinline__ float2 upk(ull v) {
    float2 f; asm("mov.b64 {%0,%1}, %2;" : "=f"(f.x), "=f"(f.y) : "l"(v)); return f;
}

__device__ __forceinline__ float gate_fn(float d) {
    // tanh(d)*sigmoid(d);  e^{-2d} = (e^{-d})^2 -> single MUFU exp
    float e1 = __expf(-d);
    float sg = __fdividef(1.f, 1.f + e1);
    float th = __fdividef(2.f, 1.f + e1 * e1) - 1.f;
    return th * sg;
}

// ---------------- start conv: h0[b][c][u] = b + W0*x[t-1] + W1*x[t] ----------------
__global__ void start_conv(const float* __restrict__ x,
                           const float* __restrict__ Wst,
                           const float* __restrict__ bst) {
    int b = blockIdx.y;
    int u = blockIdx.x * 256 + threadIdx.x;      // 0..WIN-1
    int t = (Tlen - WIN) + u;                    // >= 5120
    float x0 = x[b * Tlen + t - 1];
    float x1 = x[b * Tlen + t];
    for (int c = 0; c < RES; c++) {
        g_h[0][b][c][u] = bst[c] + Wst[2 * c] * x0 + Wst[2 * c + 1] * x1;
    }
}

// ---------------- fused layer: dilated conv GEMM -> gate -> residual GEMM ----------------
// Block: all 256 channels x BN time columns. Thread tile MR(16) x NPT(6) via f32x2.
template <int BN>
__global__ void __launch_bounds__((RES / MR) * (BN / NPT), 1)
layer_kernel(int pp,
             const float* __restrict__ Wd,   // [256][512]  (k = 2*ci + tap)
             const float* __restrict__ bd,
             const float* __restrict__ Wr,   // [256][256]
             const float* __restrict__ br,
             int dil, int u0, int layer) {
    constexpr int NTH = BN / NPT;
    constexpr int TPB = (RES / MR) * NTH;
    constexpr int NP2 = NPT / 2;

    extern __shared__ float smem[];
    float* As = smem;                    // [KT][ASTR2]  duplicated + skewed A
    float* Bs = smem + KT * ASTR2;       // [KT][BN]
    float* gs = Bs + KT * BN;            // [RES][BN]    gated activations

    const int tid = threadIdx.x;
    const int tn  = tid % NTH;
    const int tm  = tid / NTH;
    const int b   = blockIdx.y;
    const int ub  = u0 + blockIdx.x * BN;

    const float* hin  = &g_h[pp][b][0][0];
    float*       hout = &g_h[pp ^ 1][b][0][0];

    ull acc[MR][NP2];
#pragma unroll
    for (int m = 0; m < MR; m++)
#pragma unroll
        for (int q = 0; q < NP2; q++) acc[m][q] = 0ull;

    // ---- phase 1: dilated conv, K = 512 ----
    for (int k0 = 0; k0 < 2 * RES; k0 += KT) {
        __syncthreads();
        // stage A: each thread handles whole KT-strip of one out-channel row
        for (int co = tid; co < RES; co += TPB) {
            const float4* src = (const float4*)(Wd + co * (2 * RES) + k0);
            int base = 2 * co + 2 * (co >> 4);          // skew: distinct banks across tm
#pragma unroll
            for (int j = 0; j < KT / 4; j++) {
                float4 v = src[j];
                *(ull*)&As[(4 * j + 0) * ASTR2 + base] = pk2(v.x);
                *(ull*)&As[(4 * j + 1) * ASTR2 + base] = pk2(v.y);
                *(ull*)&As[(4 * j + 2) * ASTR2 + base] = pk2(v.z);
                *(ull*)&As[(4 * j + 3) * ASTR2 + base] = pk2(v.w);
            }
        }
        // stage B: rows = (ci,tap) pairs; tap0 -> t-d, tap1 -> t
        for (int idx = tid; idx < KT * BN; idx += TPB) {
            int u  = idx % BN;
            int kr = idx / BN;
            int r  = k0 + kr;
            int ci = r >> 1;
            int off = (r & 1) ? 0 : dil;
            Bs[kr * BN + u] = hin[ci * HSTR + ub + u - off];
        }
        __syncthreads();
#pragma unroll
        for (int kk = 0; kk < KT; kk++) {
            ull bb[NP2];
#pragma unroll
            for (int q = 0; q < NP2; q++)
                bb[q] = *(const ull*)&Bs[kk * BN + tn * NPT + 2 * q];
            const float* ar = &As[kk * ASTR2 + tm * (2 * MR + 2)];
#pragma unroll
            for (int m = 0; m < MR; m++) {
                ull a2 = *(const ull*)&ar[2 * m];
#pragma unroll
                for (int q = 0; q < NP2; q++) acc[m][q] = fma2(a2, bb[q], acc[m][q]);
            }
        }
    }
    __syncthreads();

    // gate + stash into SMEM, reset accumulators
#pragma unroll
    for (int m = 0; m < MR; m++) {
        int co = tm * MR + m;
        float bdv = bd[co];
#pragma unroll
        for (int q = 0; q < NP2; q++) {
            float2 v = upk(acc[m][q]);
            gs[co * BN + tn * NPT + 2 * q]     = gate_fn(v.x + bdv);
            gs[co * BN + tn * NPT + 2 * q + 1] = gate_fn(v.y + bdv);
            acc[m][q] = 0ull;
        }
    }
    __syncthreads();

    // gated column at global t = T-1 -> skip-head input
    {
        int ul = (WIN - 1) - ub;
        if (ul >= 0 && ul < BN)
            for (int c = tid; c < RES; c += TPB)
                g_gLast[layer][b][c] = gs[c * BN + ul];
    }

    // ---- phase 2: residual GEMM, K = 256, B-matrix = gs (already in SMEM) ----
    for (int k0 = 0; k0 < RES; k0 += KT) {
        __syncthreads();
        for (int co = tid; co < RES; co += TPB) {
            const float4* src = (const float4*)(Wr + co * RES + k0);
            int base = 2 * co + 2 * (co >> 4);
#pragma unroll
            for (int j = 0; j < KT / 4; j++) {
                float4 v = src[j];
                *(ull*)&As[(4 * j + 0) * ASTR2 + base] = pk2(v.x);
                *(ull*)&As[(4 * j + 1) * ASTR2 + base] = pk2(v.y);
                *(ull*)&As[(4 * j + 2) * ASTR2 + base] = pk2(v.z);
                *(ull*)&As[(4 * j + 3) * ASTR2 + base] = pk2(v.w);
            }
        }
        __syncthreads();
#pragma unroll
        for (int kk = 0; kk < KT; kk++) {
            ull bb[NP2];
#pragma unroll
            for (int q = 0; q < NP2; q++)
                bb[q] = *(const ull*)&gs[(k0 + kk) * BN + tn * NPT + 2 * q];
            const float* ar = &As[kk * ASTR2 + tm * (2 * MR + 2)];
#pragma unroll
            for (int m = 0; m < MR; m++) {
                ull a2 = *(const ull*)&ar[2 * m];
#pragma unroll
                for (int q = 0; q < NP2; q++) acc[m][q] = fma2(a2, bb[q], acc[m][q]);
            }
        }
    }

    // residual epilogue: hout = hin + Wr@g + br (write-guarded to valid window)
#pragma unroll
    for (int m = 0; m < MR; m++) {
        int co = tm * MR + m;
        float brv = br[co];
#pragma unroll
        for (int q = 0; q < NP2; q++) {
            float2 v = upk(acc[m][q]);
            int u = ub + tn * NPT + 2 * q;
            if (u < WIN)     hout[co * HSTR + u]     = hin[co * HSTR + u]     + v.x + brv;
            if (u + 1 < WIN) hout[co * HSTR + u + 1] = hin[co * HSTR + u + 1] + v.y + brv;
        }
    }
}

// ---------------- skip head: skip[b][so] = relu( sum_l (Ws[l]@gLast[l][b] + bs[l]) ) ----------------
__global__ void skip_kernel(const float* __restrict__ Ws, const float* __restrict__ bs) {
    int b = blockIdx.x;
    int w = threadIdx.x >> 5;
    int lane = threadIdx.x & 31;
    int so_base = blockIdx.y * 64 + w * 8;
    for (int oi = 0; oi < 8; oi++) {
        int so = so_base + oi;
        float v = (lane < NLAY) ? bs[lane * SKIPC + so] : 0.f;   // bias sum via lane-sum
        for (int l = 0; l < NLAY; l++) {
            const float* wr = Ws + ((size_t)l * SKIPC + so) * RES;
            const float* gg = &g_gLast[l][b][0];
#pragma unroll
            for (int k = lane; k < RES; k += 32) v += wr[k] * gg[k];
        }
#pragma unroll
        for (int s = 16; s; s >>= 1) v += __shfl_xor_sync(0xffffffffu, v, s);
        if (lane == 0) g_skip[b][so] = fmaxf(v, 0.f);
    }
}

// ---------------- end head: out = W2 @ relu(W1 @ skip + b1) + b2 ----------------
__global__ void end_kernel(const float* __restrict__ We1, const float* __restrict__ be1,
                           const float* __restrict__ We2, const float* __restrict__ be2,
                           float* __restrict__ out) {
    __shared__ float sk[SKIPC];
    __shared__ float mid[SKIPC];
    int b = blockIdx.x;
    int tid = threadIdx.x;
    int w = tid >> 5, lane = tid & 31;
    for (int i = tid; i < SKIPC; i += 256) sk[i] = g_skip[b][i];
    __syncthreads();
    for (int oi = 0; oi < 64; oi++) {
        int so = w * 64 + oi;
        const float* row = We1 + (size_t)so * SKIPC;
        float v = 0.f;
#pragma unroll
        for (int k = lane; k < SKIPC; k += 32) v += row[k] * sk[k];
#pragma unroll
        for (int s = 16; s; s >>= 1) v += __shfl_xor_sync(0xffffffffu, v, s);
        if (lane == 0) mid[so] = fmaxf(v + be1[so], 0.f);
    }
    __syncthreads();
    for (int oi = 0; oi < 32; oi++) {
        int nc = w * 32 + oi;
        const float* row = We2 + (size_t)nc * SKIPC;
        float v = 0.f;
#pragma unroll
        for (int k = lane; k < SKIPC; k += 32) v += row[k] * mid[k];
#pragma unroll
        for (int s = 16; s; s >>= 1) v += __shfl_xor_sync(0xffffffffu, v, s);
        if (lane == 0) out[b * NCLSC + nc] = v + be2[nc];
    }
}

// ---------------- host launch ----------------
static const int DILS[NLAY] = {1,2,4,8,16,32,64,128,256,512,
                               1,2,4,8,16,32,64,128,256,512,
                               1,2,4,8,16,32,64,128,256,512};

extern "C" void kernel_launch(void* const* d_in, const int* in_sizes, int n_in,
                              void* d_out, int out_size) {
    (void)in_sizes; (void)n_in; (void)out_size;
    const float* x   = (const float*)d_in[0];
    const float* Wst = (const float*)d_in[1];
    const float* bst = (const float*)d_in[2];
    const float* Wd  = (const float*)d_in[3];
    const float* bd  = (const float*)d_in[4];
    const float* Wr  = (const float*)d_in[5];
    const float* br  = (const float*)d_in[6];
    const float* Ws  = (const float*)d_in[7];
    const float* bs  = (const float*)d_in[8];
    const float* We1 = (const float*)d_in[9];
    const float* be1 = (const float*)d_in[10];
    const float* We2 = (const float*)d_in[11];
    const float* be2 = (const float*)d_in[12];
    float* out = (float*)d_out;

    const size_t sm96 = (size_t)(KT * ASTR2 + KT * 96 + RES * 96) * sizeof(float);
    const size_t sm48 = (size_t)(KT * ASTR2 + KT * 48 + RES * 48) * sizeof(float);
    cudaFuncSetAttribute((const void*)layer_kernel<96>,
                         cudaFuncAttributeMaxDynamicSharedMemorySize, (int)sm96);
    cudaFuncSetAttribute((const void*)layer_kernel<48>,
                         cudaFuncAttributeMaxDynamicSharedMemorySize, (int)sm48);

    start_conv<<<dim3(WIN / 256, Bsz), 256>>>(x, Wst, bst);

    int suf[NLAY + 1];
    suf[NLAY] = 0;
    for (int i = NLAY - 1; i >= 0; i--) suf[i] = suf[i + 1] + DILS[i];

    for (int i = 0; i < NLAY; i++) {
        int N  = 1 + suf[i + 1];        // columns this layer must produce
        int u0 = WIN - N;
        int pp = i & 1;
        const float* wd  = Wd + (size_t)i * RES * RES * 2;
        const float* bdp = bd + (size_t)i * RES;
        const float* wr  = Wr + (size_t)i * RES * RES;
        const float* brp = br + (size_t)i * RES;
        if (N > 1776) {
            int gx = (N + 95) / 96;
            layer_kernel<96><<<dim3(gx, Bsz), 256, sm96>>>(pp, wd, bdp, wr, brp, DILS[i], u0, i);
        } else {
            int gx = (N + 47) / 48;
            layer_kernel<48><<<dim3(gx, Bsz), 128, sm48>>>(pp, wd, bdp, wr, brp, DILS[i], u0, i);
        }
    }

    skip_kernel<<<dim3(Bsz, SKIPC / 64), 256>>>(Ws, bs);
    end_kernel<<<Bsz, 256>>>(We1, be1, We2, be2, out);
}

// round 3
// speedup vs baseline: 1.8838x; 1.8838x over previous
#include <cuda_runtime.h>

#define Tlen  8192
#define Bsz   4
#define RES   256
#define SKIPC 512
#define NCLSC 256
#define NLAY  30
#define WIN   3072
#define HSTR  3200
#define KT    32
#define ASTR  264

typedef unsigned long long ull;

// ---------------- device scratch (allocation-free) ----------------
__device__ float g_h[2][Bsz][RES][HSTR];       // ping-pong hidden state; pads stay zero
__device__ float g_WdT[NLAY][2 * RES][RES];    // transposed conv weights  [k][co]
__device__ float g_WrT[NLAY][RES][RES];        // transposed residual weights
__device__ float g_gLast[NLAY][Bsz][RES];      // gated activation at t = T-1 per layer
__device__ float g_skip[Bsz][SKIPC];

// ---------------- f32x2 helpers ----------------
__device__ __forceinline__ ull pk2(float v) {
    ull r; asm("mov.b64 %0, {%1,%2};" : "=l"(r) : "f"(v), "f"(v)); return r;
}
__device__ __forceinline__ ull fma2(ull a, ull b, ull c) {
    ull d; asm("fma.rn.f32x2 %0, %1, %2, %3;" : "=l"(d) : "l"(a), "l"(b), "l"(c)); return d;
}
__device__ __forceinline__ float2 upk(ull v) {
    float2 f; asm("mov.b64 {%0,%1}, %2;" : "=f"(f.x), "=f"(f.y) : "l"(v)); return f;
}
__device__ __forceinline__ float gate_fn(float d) {
    float e1 = __expf(-d);
    float sg = __fdividef(1.f, 1.f + e1);
    float th = __fdividef(2.f, 1.f + e1 * e1) - 1.f;
    return th * sg;
}
__device__ __forceinline__ unsigned su32(const void* p) {
    return (unsigned)__cvta_generic_to_shared(p);
}

#define CPA16(d, s) asm volatile("cp.async.cg.shared.global [%0],[%1],16;\n" :: "r"(d), "l"(s))
#define CPA4(d, s)  asm volatile("cp.async.ca.shared.global [%0],[%1],4;\n"  :: "r"(d), "l"(s))
#define CPCOMMIT()  asm volatile("cp.async.commit_group;\n")
#define CPWAIT0()   asm volatile("cp.async.wait_group 0;\n" ::: "memory")

// ---------------- weight transpose prep (runs every call; ~20us) ----------------
__global__ void transpose_prep(const float* __restrict__ Wd, const float* __restrict__ Wr) {
    __shared__ float t[32][33];
    int z = blockIdx.z;
    int lay = z % NLAY, which = z / NLAY;
    const float* src; float* dst; int K;
    if (which == 0) { K = 512; src = Wd + (size_t)lay * RES * 512; dst = &g_WdT[lay][0][0]; }
    else            { K = 256; src = Wr + (size_t)lay * RES * 256; dst = &g_WrT[lay][0][0];
                      if ((int)blockIdx.x >= K / 32) return; }
    int k0 = blockIdx.x * 32, c0 = blockIdx.y * 32;
    int tx = threadIdx.x, ty = threadIdx.y;
    for (int j = 0; j < 32; j += 8)
        t[ty + j][tx] = src[(size_t)(c0 + ty + j) * K + k0 + tx];
    __syncthreads();
    for (int j = 0; j < 32; j += 8)
        dst[(size_t)(k0 + ty + j) * RES + c0 + tx] = t[tx][ty + j];
}

// ---------------- start conv ----------------
__global__ void start_conv(const float* __restrict__ x,
                           const float* __restrict__ Wst,
                           const float* __restrict__ bst) {
    int b = blockIdx.y;
    int u = blockIdx.x * 256 + threadIdx.x;
    int t = (Tlen - WIN) + u;
    float x0 = x[b * Tlen + t - 1];
    float x1 = x[b * Tlen + t];
    for (int c = 0; c < RES; c++)
        g_h[0][b][c][u] = bst[c] + Wst[2 * c] * x0 + Wst[2 * c + 1] * x1;
}

// ---------------- fused layer kernel ----------------
// Thread tile: 8 channels (4 f32x2 co-pairs) x NPT time columns. BN = (TPB/32)*NPT.
template <int TPB, int NPT>
__global__ void __launch_bounds__(TPB, 1)
layer_kernel(int pp,
             const float* __restrict__ WdT, const float* __restrict__ bd,
             const float* __restrict__ WrT, const float* __restrict__ br,
             int dil, int u0, int layer) {
    constexpr int NTH = TPB / 32;
    constexpr int BN  = NTH * NPT;
    constexpr int NP2 = NPT / 2;

    extern __shared__ float smem[];
    float* As0 = smem;                               // 2 x [KT][ASTR]
    float* Bs0 = smem + 2 * KT * ASTR;               // 2 x [KT][BN]
    float* gs  = smem + 2 * KT * ASTR + 2 * KT * BN; // [RES][BN]

    const int tid = threadIdx.x;
    const int tn  = tid % NTH;
    const int tm  = tid / NTH;           // 0..31
    const int b   = blockIdx.y;
    const int ub  = u0 + blockIdx.x * BN;

    const float* hin  = &g_h[pp][b][0][0];
    float*       hout = &g_h[pp ^ 1][b][0][0];

    ull acc[4][NPT];
#pragma unroll
    for (int p = 0; p < 4; p++)
#pragma unroll
        for (int u = 0; u < NPT; u++) acc[p][u] = 0ull;

    // --- staging helpers (cp.async) ---
    auto stageA = [&](int s, const float* src) {   // 32 rows x 256 floats, contiguous
        float* dstb = As0 + s * KT * ASTR;
#pragma unroll
        for (int c = tid; c < KT * 64; c += TPB) {
            int kk = c >> 6, j = (c & 63) << 2;
            CPA16(su32(dstb + kk * ASTR + j), src + kk * RES + j);
        }
    };
    auto stageB = [&](int s, int k0) {
        float* dstb = Bs0 + s * KT * BN;
#pragma unroll
        for (int e = tid; e < KT * BN; e += TPB) {
            int kr = e / BN, u = e - kr * BN;
            int r  = k0 + kr;
            int ci = r >> 1;
            int off = (r & 1) ? 0 : dil;
            CPA4(su32(dstb + kr * BN + u), hin + ci * HSTR + (ub + u - off));
        }
    };

    // --- compute macro over one staged k-tile ---
    auto compute = [&](const float* A, const float* B, int bstride) {
#pragma unroll
        for (int kk = 0; kk < KT; kk++) {
            const float* ar = A + kk * ASTR + tm * 8;
            ulonglong2 av0 = *(const ulonglong2*)ar;
            ulonglong2 av1 = *(const ulonglong2*)(ar + 4);
            ull a2[4] = {av0.x, av0.y, av1.x, av1.y};
            ull b2[NPT];
#pragma unroll
            for (int q = 0; q < NP2; q++) {
                float2 bf = *(const float2*)(B + kk * bstride + tn * NPT + 2 * q);
                b2[2 * q]     = pk2(bf.x);
                b2[2 * q + 1] = pk2(bf.y);
            }
#pragma unroll
            for (int p = 0; p < 4; p++)
#pragma unroll
                for (int u = 0; u < NPT; u++) acc[p][u] = fma2(a2[p], b2[u], acc[p][u]);
        }
    };

    // ---- phase 1: dilated conv, K = 512 (16 tiles) ----
    stageA(0, WdT); stageB(0, 0); CPCOMMIT();
    int cur = 0;
    for (int t = 0; t < 16; t++) {
        CPWAIT0(); __syncthreads();
        if (t + 1 < 16) { stageA(cur ^ 1, WdT + (t + 1) * KT * RES); stageB(cur ^ 1, (t + 1) * KT); }
        else            { stageA(cur ^ 1, WrT); }   // prefetch phase-2 tile 0
        CPCOMMIT();
        compute(As0 + cur * KT * ASTR, Bs0 + cur * KT * BN, BN);
        cur ^= 1;
    }

    // ---- gate -> gs, skip column extraction, reset acc ----
    {
        int ul = (WIN - 1) - ub - tn * NPT;     // local column index of t = T-1, if owned
#pragma unroll
        for (int p = 0; p < 4; p++) {
            int co = tm * 8 + 2 * p;
            float bd0 = bd[co], bd1 = bd[co + 1];
#pragma unroll
            for (int u = 0; u < NPT; u++) {
                float2 v = upk(acc[p][u]);
                float g0 = gate_fn(v.x + bd0);
                float g1 = gate_fn(v.y + bd1);
                gs[co * BN + tn * NPT + u]       = g0;
                gs[(co + 1) * BN + tn * NPT + u] = g1;
                if (u == ul) { g_gLast[layer][b][co] = g0; g_gLast[layer][b][co + 1] = g1; }
                acc[p][u] = 0ull;
            }
        }
    }

    // ---- phase 2: residual GEMM, K = 256 (8 tiles), B = gs in SMEM ----
    for (int t = 0; t < 8; t++) {
        CPWAIT0(); __syncthreads();    // also publishes gs writes before first read
        if (t + 1 < 8) stageA(cur ^ 1, WrT + (t + 1) * KT * RES);
        CPCOMMIT();
        compute(As0 + cur * KT * ASTR, gs + t * KT * BN, BN);
        cur ^= 1;
    }

    // ---- residual epilogue ----
#pragma unroll
    for (int p = 0; p < 4; p++) {
        int co = tm * 8 + 2 * p;
        float br0 = br[co], br1 = br[co + 1];
#pragma unroll
        for (int u = 0; u < NPT; u++) {
            float2 v = upk(acc[p][u]);
            int uu = ub + tn * NPT + u;
            if (uu < WIN) {
                hout[co * HSTR + uu]       = hin[co * HSTR + uu]       + v.x + br0;
                hout[(co + 1) * HSTR + uu] = hin[(co + 1) * HSTR + uu] + v.y + br1;
            }
        }
    }
}

// ---------------- skip head ----------------
__global__ void skip_kernel(const float* __restrict__ Ws, const float* __restrict__ bs) {
    int b = blockIdx.x;
    int w = threadIdx.x >> 5;
    int lane = threadIdx.x & 31;
    int so_base = blockIdx.y * 64 + w * 8;
    for (int oi = 0; oi < 8; oi++) {
        int so = so_base + oi;
        float v = (lane < NLAY) ? bs[lane * SKIPC + so] : 0.f;
        for (int l = 0; l < NLAY; l++) {
            const float* wr = Ws + ((size_t)l * SKIPC + so) * RES;
            const float* gg = &g_gLast[l][b][0];
#pragma unroll
            for (int k = lane; k < RES; k += 32) v += wr[k] * gg[k];
        }
#pragma unroll
        for (int s = 16; s; s >>= 1) v += __shfl_xor_sync(0xffffffffu, v, s);
        if (lane == 0) g_skip[b][so] = fmaxf(v, 0.f);
    }
}

// ---------------- end head ----------------
__global__ void end_kernel(const float* __restrict__ We1, const float* __restrict__ be1,
                           const float* __restrict__ We2, const float* __restrict__ be2,
                           float* __restrict__ out) {
    __shared__ float sk[SKIPC];
    __shared__ float mid[SKIPC];
    int b = blockIdx.x;
    int tid = threadIdx.x;
    int w = tid >> 5, lane = tid & 31;
    for (int i = tid; i < SKIPC; i += 256) sk[i] = g_skip[b][i];
    __syncthreads();
    for (int oi = 0; oi < 64; oi++) {
        int so = w * 64 + oi;
        const float* row = We1 + (size_t)so * SKIPC;
        float v = 0.f;
#pragma unroll
        for (int k = lane; k < SKIPC; k += 32) v += row[k] * sk[k];
#pragma unroll
        for (int s = 16; s; s >>= 1) v += __shfl_xor_sync(0xffffffffu, v, s);
        if (lane == 0) mid[so] = fmaxf(v + be1[so], 0.f);
    }
    __syncthreads();
    for (int oi = 0; oi < 32; oi++) {
        int nc = w * 32 + oi;
        const float* row = We2 + (size_t)nc * SKIPC;
        float v = 0.f;
#pragma unroll
        for (int k = lane; k < SKIPC; k += 32) v += row[k] * mid[k];
#pragma unroll
        for (int s = 16; s; s >>= 1) v += __shfl_xor_sync(0xffffffffu, v, s);
        if (lane == 0) out[b * NCLSC + nc] = v + be2[nc];
    }
}

// ---------------- host ----------------
static const int DILS[NLAY] = {1,2,4,8,16,32,64,128,256,512,
                               1,2,4,8,16,32,64,128,256,512,
                               1,2,4,8,16,32,64,128,256,512};

static inline size_t smem_for(int BN) {
    return (size_t)(2 * KT * ASTR + 2 * KT * BN + RES * BN) * sizeof(float);
}

extern "C" void kernel_launch(void* const* d_in, const int* in_sizes, int n_in,
                              void* d_out, int out_size) {
    (void)in_sizes; (void)n_in; (void)out_size;
    const float* x   = (const float*)d_in[0];
    const float* Wst = (const float*)d_in[1];
    const float* bst = (const float*)d_in[2];
    const float* Wd  = (const float*)d_in[3];
    const float* bd  = (const float*)d_in[4];
    const float* Wr  = (const float*)d_in[5];
    const float* br  = (const float*)d_in[6];
    const float* Ws  = (const float*)d_in[7];
    const float* bs  = (const float*)d_in[8];
    const float* We1 = (const float*)d_in[9];
    const float* be1 = (const float*)d_in[10];
    const float* We2 = (const float*)d_in[11];
    const float* be2 = (const float*)d_in[12];
    float* out = (float*)d_out;

    cudaFuncSetAttribute((const void*)layer_kernel<512, 6>, cudaFuncAttributeMaxDynamicSharedMemorySize, (int)smem_for(96));
    cudaFuncSetAttribute((const void*)layer_kernel<384, 6>, cudaFuncAttributeMaxDynamicSharedMemorySize, (int)smem_for(72));
    cudaFuncSetAttribute((const void*)layer_kernel<512, 4>, cudaFuncAttributeMaxDynamicSharedMemorySize, (int)smem_for(64));
    cudaFuncSetAttribute((const void*)layer_kernel<384, 4>, cudaFuncAttributeMaxDynamicSharedMemorySize, (int)smem_for(48));
    cudaFuncSetAttribute((const void*)layer_kernel<512, 2>, cudaFuncAttributeMaxDynamicSharedMemorySize, (int)smem_for(32));
    cudaFuncSetAttribute((const void*)layer_kernel<384, 2>, cudaFuncAttributeMaxDynamicSharedMemorySize, (int)smem_for(24));
    cudaFuncSetAttribute((const void*)layer_kernel<256, 2>, cudaFuncAttributeMaxDynamicSharedMemorySize, (int)smem_for(16));
    cudaFuncSetAttribute((const void*)layer_kernel<128, 2>, cudaFuncAttributeMaxDynamicSharedMemorySize, (int)smem_for(8));

    transpose_prep<<<dim3(16, 8, 2 * NLAY), dim3(32, 8)>>>(Wd, Wr);
    start_conv<<<dim3(WIN / 256, Bsz), 256>>>(x, Wst, bst);

    int suf[NLAY + 1];
    suf[NLAY] = 0;
    for (int i = NLAY - 1; i >= 0; i--) suf[i] = suf[i + 1] + DILS[i];

    static const int BNS[8] = {8, 16, 24, 32, 48, 64, 72, 96};

    for (int i = 0; i < NLAY; i++) {
        int N  = 1 + suf[i + 1];
        int u0 = WIN - N;
        int pp = i & 1;
        const float* wdt = &g_WdT[0][0][0];   // placeholder; real ptr below via offset
        (void)wdt;
        int BN = 96;
        for (int j = 0; j < 8; j++) {
            if ((N + BNS[j] - 1) / BNS[j] <= 37) { BN = BNS[j]; break; }
        }
        int gx = (N + BN - 1) / BN;
        const float* bdp = bd + (size_t)i * RES;
        const float* brp = br + (size_t)i * RES;

        // device-global weight slices: pass base pointers; kernel indexes by layer
        // (we pass the transposed arrays directly via their device addresses)
        float* wdT_dev; float* wrT_dev;
        cudaGetSymbolAddress((void**)&wdT_dev, g_WdT);
        cudaGetSymbolAddress((void**)&wrT_dev, g_WrT);
        const float* wdt_l = wdT_dev + (size_t)i * 2 * RES * RES;
        const float* wrt_l = wrT_dev + (size_t)i * RES * RES;

        dim3 grid(gx, Bsz);
        size_t sm = smem_for(BN);
        switch (BN) {
            case 96: layer_kernel<512, 6><<<grid, 512, sm>>>(pp, wdt_l, bdp, wrt_l, brp, DILS[i], u0, i); break;
            case 72: layer_kernel<384, 6><<<grid, 384, sm>>>(pp, wdt_l, bdp, wrt_l, brp, DILS[i], u0, i); break;
            case 64: layer_kernel<512, 4><<<grid, 512, sm>>>(pp, wdt_l, bdp, wrt_l, brp, DILS[i], u0, i); break;
            case 48: layer_kernel<384, 4><<<grid, 384, sm>>>(pp, wdt_l, bdp, wrt_l, brp, DILS[i], u0, i); break;
            case 32: layer_kernel<512, 2><<<grid, 512, sm>>>(pp, wdt_l, bdp, wrt_l, brp, DILS[i], u0, i); break;
            case 24: layer_kernel<384, 2><<<grid, 384, sm>>>(pp, wdt_l, bdp, wrt_l, brp, DILS[i], u0, i); break;
            case 16: layer_kernel<256, 2><<<grid, 256, sm>>>(pp, wdt_l, bdp, wrt_l, brp, DILS[i], u0, i); break;
            default: layer_kernel<128, 2><<<grid, 128, sm>>>(pp, wdt_l, bdp, wrt_l, brp, DILS[i], u0, i); break;
        }
    }

    skip_kernel<<<dim3(Bsz, SKIPC / 64), 256>>>(Ws, bs);
    end_kernel<<<Bsz, 256>>>(We1, be1, We2, be2, out);
}